// round 14
// baseline (speedup 1.0000x reference)
#include <cuda_runtime.h>
#include <cuda_fp16.h>
#include <mma.h>
#include <math_constants.h>
#include <cstdint>
#include <cstddef>

using namespace nvcuda;

// Problem constants
#define KB 8
#define KS 4096
#define KH 16
#define KD 1024
#define KM 32768      // B*S
#define KW 16

// Device scratch (allocation-free rules)
__device__ __align__(256) __half g_qkvh [(size_t)KM * 3072];  // fp16 QKV (+bias)
__device__ __align__(256) __half g_xh   [(size_t)KM * KD];    // x in fp16
__device__ __align__(256) __half g_attnh[(size_t)KM * KD];    // attention out fp16
__device__ __align__(256) __half g_wqkvh[1024 * 3072];        // Wqkv fp16 [K][N]
__device__ __align__(256) __half g_woh  [1024 * 1024];        // Wo   fp16 [K][N]

// ---------------------------------------------------------------------------
// cp.async helpers
// ---------------------------------------------------------------------------
__device__ __forceinline__ uint32_t smem_u32(const void* p) {
    return (uint32_t)__cvta_generic_to_shared((void*)p);
}
__device__ __forceinline__ void cp_async16(uint32_t dst, const void* src) {
    asm volatile("cp.async.cg.shared.global [%0], [%1], 16;\n" :: "r"(dst), "l"(src) : "memory");
}
__device__ __forceinline__ void cp_commit() { asm volatile("cp.async.commit_group;\n" ::: "memory"); }
__device__ __forceinline__ void cp_wait0()  { asm volatile("cp.async.wait_group 0;\n" ::: "memory"); }
__device__ __forceinline__ void cp_wait1()  { asm volatile("cp.async.wait_group 1;\n" ::: "memory"); }

// ---------------------------------------------------------------------------
// fp32 -> fp16 convert
// ---------------------------------------------------------------------------
__global__ void f2h(const float* __restrict__ in, __half* __restrict__ out, int n)
{
    int i = (blockIdx.x * blockDim.x + threadIdx.x) * 4;
    const int stride = gridDim.x * blockDim.x * 4;
    for (; i < n; i += stride) {
        float4 v = *(const float4*)(in + i);
        __half2 h0 = __floats2half2_rn(v.x, v.y);
        __half2 h1 = __floats2half2_rn(v.z, v.w);
        uint2 u;
        u.x = *reinterpret_cast<uint32_t*>(&h0);
        u.y = *reinterpret_cast<uint32_t*>(&h1);
        *(uint2*)(out + i) = u;
    }
}

// ---------------------------------------------------------------------------
// fp16 WMMA GEMM, 2 n-tiles per CTA:
//   for tt in {0,1}: C[m0:m0+128, n0+tt*128 : +128] = A @ B + bias
// CTA 128 rows, BK=64 (16 iters/tile), 8 warps (2x4), warp tile 64x32.
// 3-stage cp.async ring, 1 sync/iter. Tile-0 epilogue overlaps tile-1
// prologue fills; epilogue stages into ring slot 2 (dead then).
// 2 CTAs/SM.
// ---------------------------------------------------------------------------
#define G_LDA 72                     // A row stride (halves)
#define G_LDB 136                    // B row stride (halves)
#define G_ASZ (128 * G_LDA * 2)      // 18432
#define G_STG (G_ASZ + 64 * G_LDB * 2)   // 35840
#define G_SMEM (3 * G_STG)           // 107520
#define NTILE 2

template<bool HALF_OUT>
__global__ __launch_bounds__(256, 2)
void gemm_2t(const __half* __restrict__ A, const __half* __restrict__ Bw,
             const float* __restrict__ bias, void* __restrict__ Cv,
             int N, int K)
{
    extern __shared__ __align__(16) char sm[];
    const uint32_t sbase = smem_u32(sm);
    const int tid    = threadIdx.x;
    const int warpId = tid >> 5;
    const int lane   = tid & 31;
    const int warpM  = warpId & 1;
    const int warpN  = warpId >> 1;
    const int m0  = blockIdx.y * 128;
    const int nb0 = blockIdx.x * 128 * NTILE;
    const int nT  = K >> 6;          // 16

    auto fillA = [&](int t, int slot) {
        const int k0 = t << 6;
        const uint32_t sb = sbase + (uint32_t)slot * G_STG;
#pragma unroll
        for (int u = 0; u < 4; u++) {
            int i = tid + u * 256;
            int r = i >> 3, c = (i & 7) * 8;
            cp_async16(sb + r * (G_LDA * 2) + c * 2, A + (size_t)(m0 + r) * K + k0 + c);
        }
    };
    auto fillB = [&](int t, int slot, int n0) {
        const int k0 = t << 6;
        const uint32_t sb = sbase + (uint32_t)slot * G_STG;
#pragma unroll
        for (int u = 0; u < 4; u++) {
            int i = tid + u * 256;
            int r = i >> 4, c = (i & 15) * 8;
            cp_async16(sb + G_ASZ + r * (G_LDB * 2) + c * 2,
                       Bw + (size_t)(k0 + r) * N + n0 + c);
        }
    };

    // prologue: chunks 0,1 of tile 0
    fillA(0, 0); fillB(0, 0, nb0); cp_commit();
    fillA(1, 1); fillB(1, 1, nb0); cp_commit();

    wmma::fragment<wmma::accumulator, 16, 16, 16, float> cf[4][2];

    for (int tt = 0; tt < NTILE; tt++) {
        const int n0 = nb0 + tt * 128;

#pragma unroll
        for (int i = 0; i < 4; i++)
#pragma unroll
            for (int j = 0; j < 2; j++)
                wmma::fill_fragment(cf[i][j], 0.0f);

        for (int t = 0; t < nT; t++) {
            const int slot = t % 3;
            if (t + 1 < nT) cp_wait1(); else cp_wait0();
            __syncthreads();
            if (t + 2 < nT) {
                const int fs = (t + 2) % 3;
                fillA(t + 2, fs); fillB(t + 2, fs, n0); cp_commit();
            }

            const __half* As_ = (const __half*)(sm + (size_t)slot * G_STG);
            const __half* Bs_ = (const __half*)(sm + (size_t)slot * G_STG + G_ASZ);
#pragma unroll
            for (int kk = 0; kk < 4; kk++) {
                wmma::fragment<wmma::matrix_b, 16, 16, 16, __half, wmma::row_major> bf[2];
#pragma unroll
                for (int j = 0; j < 2; j++)
                    wmma::load_matrix_sync(bf[j], &Bs_[(kk * 16) * G_LDB + warpN * 32 + j * 16], G_LDB);
#pragma unroll
                for (int i = 0; i < 4; i++) {
                    wmma::fragment<wmma::matrix_a, 16, 16, 16, __half, wmma::row_major> af;
                    wmma::load_matrix_sync(af, &As_[(warpM * 64 + i * 16) * G_LDA + kk * 16], G_LDA);
#pragma unroll
                    for (int j = 0; j < 2; j++)
                        wmma::mma_sync(cf[i][j], af, bf[j], cf[i][j]);
                }
            }
        }

        __syncthreads();   // all warps done reading ring slots for this tile

        // boundary prefetch: chunks 0,1 of next tile into slots 0,1
        // (overlaps this tile's epilogue with the next tile's DRAM latency)
        if (tt + 1 < NTILE) {
            const int n1 = nb0 + (tt + 1) * 128;
            fillA(0, 0); fillB(0, 0, n1); cp_commit();
            fillA(1, 1); fillB(1, 1, n1); cp_commit();
        }

        // epilogue: per-warp staging in ring slot 2 (dead here; next-tile
        // fills target slots 0,1 only; slot 2 refilled only after the
        // next tile's t=0 __syncthreads)
        float* stg = (float*)(sm + 2 * (size_t)G_STG) + warpId * 320;
        const int r  = lane >> 1;
        const int c8 = (lane & 1) * 8;
#pragma unroll
        for (int j = 0; j < 2; j++) {
            const float* bp = bias + n0 + warpN * 32 + j * 16 + c8;
            const float4 b0 = *(const float4*)bp;
            const float4 b1 = *(const float4*)(bp + 4);
#pragma unroll
            for (int i = 0; i < 4; i++) {
                wmma::store_matrix_sync(stg, cf[i][j], 20, wmma::mem_row_major);
                __syncwarp();
                const float* s = stg + r * 20 + c8;
                float v0 = s[0] + b0.x, v1 = s[1] + b0.y, v2 = s[2] + b0.z, v3 = s[3] + b0.w;
                float v4 = s[4] + b1.x, v5 = s[5] + b1.y, v6 = s[6] + b1.z, v7 = s[7] + b1.w;
                const size_t row = (size_t)(m0 + warpM * 64 + i * 16 + r);
                const int    col = n0 + warpN * 32 + j * 16 + c8;
                if (HALF_OUT) {
                    __half2 h0 = __floats2half2_rn(v0, v1);
                    __half2 h1 = __floats2half2_rn(v2, v3);
                    __half2 h2 = __floats2half2_rn(v4, v5);
                    __half2 h3 = __floats2half2_rn(v6, v7);
                    uint4 u;
                    u.x = *reinterpret_cast<uint32_t*>(&h0);
                    u.y = *reinterpret_cast<uint32_t*>(&h1);
                    u.z = *reinterpret_cast<uint32_t*>(&h2);
                    u.w = *reinterpret_cast<uint32_t*>(&h3);
                    *(uint4*)((__half*)Cv + row * N + col) = u;
                } else {
                    *(float4*)((float*)Cv + row * N + col)     = make_float4(v0, v1, v2, v3);
                    *(float4*)((float*)Cv + row * N + col + 4) = make_float4(v4, v5, v6, v7);
                }
                __syncwarp();
            }
        }

        if (tt + 1 < NTILE)
            __syncthreads();   // epilogue's slot-2 reads done before next tile refills it
    }
}

// ---------------------------------------------------------------------------
// WMMA sliding-window attention, 256 threads (8 warps) per 64-query block.
// (unchanged from round 11)
// ---------------------------------------------------------------------------
#define AQ_OFF 0
#define AK_OFF 9216
#define AV_OFF 23040
#define AS_OFF 36864
#define ATT_SMEM 62464

__global__ __launch_bounds__(256)
void attn_wmma()
{
    extern __shared__ __align__(16) char sm[];
    __half* Qh = (__half*)(sm + AQ_OFF);
    __half* Kh = (__half*)(sm + AK_OFF);
    __half* Vh = (__half*)(sm + AV_OFF);
    float*  Sf = (float*)(sm + AS_OFF);
    __half* Ph = (__half*)(sm + AK_OFF);   // overlays K (dead after QK)

    const int b  = blockIdx.z;
    const int h  = blockIdx.y;
    const int s0 = blockIdx.x * 64;
    const int tid  = threadIdx.x;
    const int w    = tid >> 5;

    const __half* qbase = g_qkvh + (size_t)(b * KS) * 3072 + h * 192;
#pragma unroll
    for (int u = 0; u < 2; u++) {
        int i = tid + u * 256;
        int r = i >> 3, c = (i & 7) * 8;
        *(uint4*)(Qh + r * 72 + c) = *(const uint4*)(qbase + (size_t)(s0 + r) * 3072 + c);
    }
#pragma unroll
    for (int u = 0; u < 3; u++) {
        int i = tid + u * 256;
        int r = i >> 3, c = (i & 7) * 8;
        int key = s0 - KW + r;
        key = key < 0 ? 0 : (key >= KS ? KS - 1 : key);
        *(uint4*)(Kh + r * 72 + c) = *(const uint4*)(qbase + (size_t)key * 3072 + 64 + c);
    }
#pragma unroll
    for (int u = 0; u < 3; u++) {
        int i = tid + u * 256;
        int r = i >> 3, c = (i & 7) * 8;
        int key = s0 - KW + r;
        key = key < 0 ? 0 : (key >= KS ? KS - 1 : key);
        *(uint4*)(Vh + r * 72 + c) = *(const uint4*)(qbase + (size_t)key * 3072 + 128 + c);
    }
    __syncthreads();

    // S = Q @ K^T
    {
        const int wr = (w & 3) * 16;
        const int nb = (w >> 2) * 3;
        wmma::fragment<wmma::matrix_a, 16, 16, 16, __half, wmma::row_major> af[4];
#pragma unroll
        for (int k = 0; k < 4; k++)
            wmma::load_matrix_sync(af[k], &Qh[wr * 72 + k * 16], 72);
#pragma unroll
        for (int nn = 0; nn < 3; nn++) {
            const int n = nb + nn;
            wmma::fragment<wmma::accumulator, 16, 16, 16, float> sc;
            wmma::fill_fragment(sc, 0.0f);
#pragma unroll
            for (int k = 0; k < 4; k++) {
                wmma::fragment<wmma::matrix_b, 16, 16, 16, __half, wmma::col_major> bf;
                wmma::load_matrix_sync(bf, &Kh[(n * 16) * 72 + k * 16], 72);
                wmma::mma_sync(sc, af[k], bf, sc);
            }
            wmma::store_matrix_sync(&Sf[wr * 100 + n * 16], sc, 100, wmma::mem_row_major);
        }
    }
    __syncthreads();

    // masked softmax
    {
        const int row = tid >> 2;
        const int sub = tid & 3;
        int jlo = row;
        if (s0 - KW + jlo < 0) jlo = KW - s0;
        int jhi = row + 32;
        const int jmax = KS - 1 - s0 + KW;
        if (jhi > jmax) jhi = jmax;
        const int ja = sub * 24;
        const int lo = jlo > ja ? jlo : ja;
        const int hi = jhi < ja + 23 ? jhi : ja + 23;

        float* Srow = Sf + row * 100;
        float m = -1e30f;
        for (int j = lo; j <= hi; j++) m = fmaxf(m, Srow[j]);
        m = fmaxf(m, __shfl_xor_sync(0xffffffffu, m, 1));
        m = fmaxf(m, __shfl_xor_sync(0xffffffffu, m, 2));
        float s = 0.f;
        for (int j = lo; j <= hi; j++) {
            float e = __expf(0.125f * (Srow[j] - m));
            Srow[j] = e;
            s += e;
        }
        s += __shfl_xor_sync(0xffffffffu, s, 1);
        s += __shfl_xor_sync(0xffffffffu, s, 2);
        const float inv = 1.0f / s;
        __half* Prow = Ph + row * 104;
        for (int j = ja; j < ja + 24; j++) {
            float p = (j >= lo && j <= hi) ? Srow[j] * inv : 0.f;
            Prow[j] = __float2half(p);
        }
    }
    __syncthreads();

    // O = P @ V
    {
        const int wr = (w & 3) * 16;
        const int ch = (w >> 2);
        wmma::fragment<wmma::accumulator, 16, 16, 16, float> of[2];
#pragma unroll
        for (int n = 0; n < 2; n++) wmma::fill_fragment(of[n], 0.0f);
#pragma unroll
        for (int k = 0; k < 6; k++) {
            wmma::fragment<wmma::matrix_a, 16, 16, 16, __half, wmma::row_major> af;
            wmma::load_matrix_sync(af, &Ph[wr * 104 + k * 16], 104);
#pragma unroll
            for (int n = 0; n < 2; n++) {
                wmma::fragment<wmma::matrix_b, 16, 16, 16, __half, wmma::row_major> bf;
                wmma::load_matrix_sync(bf, &Vh[(k * 16) * 72 + (ch * 2 + n) * 16], 72);
                wmma::mma_sync(of[n], af, bf, of[n]);
            }
        }
        float* stg = (float*)(sm + AS_OFF) + w * 320;
        const int lane = tid & 31;
        const int r  = lane >> 1;
        const int c8 = (lane & 1) * 8;
#pragma unroll
        for (int n = 0; n < 2; n++) {
            wmma::store_matrix_sync(stg, of[n], 20, wmma::mem_row_major);
            __syncwarp();
            const float* sp = stg + r * 20 + c8;
            __half2 h0 = __floats2half2_rn(sp[0], sp[1]);
            __half2 h1 = __floats2half2_rn(sp[2], sp[3]);
            __half2 h2 = __floats2half2_rn(sp[4], sp[5]);
            __half2 h3 = __floats2half2_rn(sp[6], sp[7]);
            uint4 u;
            u.x = *reinterpret_cast<uint32_t*>(&h0);
            u.y = *reinterpret_cast<uint32_t*>(&h1);
            u.z = *reinterpret_cast<uint32_t*>(&h2);
            u.w = *reinterpret_cast<uint32_t*>(&h3);
            *(uint4*)(g_attnh + (size_t)(b * KS + s0 + wr + r) * KD
                               + h * 64 + (ch * 2 + n) * 16 + c8) = u;
            __syncwarp();
        }
    }
}

// ---------------------------------------------------------------------------
extern "C" void kernel_launch(void* const* d_in, const int* in_sizes, int n_in,
                              void* d_out, int out_size)
{
    const float* x    = (const float*)d_in[0];
    const float* Wqkv = (const float*)d_in[1];
    const float* bqkv = (const float*)d_in[2];
    const float* Wo   = (const float*)d_in[3];
    const float* bo   = (const float*)d_in[4];
    float* out = (float*)d_out;

    void *p_qkvh, *p_xh, *p_attnh, *p_wqkvh, *p_woh;
    cudaGetSymbolAddress(&p_qkvh,  g_qkvh);
    cudaGetSymbolAddress(&p_xh,    g_xh);
    cudaGetSymbolAddress(&p_attnh, g_attnh);
    cudaGetSymbolAddress(&p_wqkvh, g_wqkvh);
    cudaGetSymbolAddress(&p_woh,   g_woh);

    cudaFuncSetAttribute(gemm_2t<true>,  cudaFuncAttributeMaxDynamicSharedMemorySize, G_SMEM);
    cudaFuncSetAttribute(gemm_2t<false>, cudaFuncAttributeMaxDynamicSharedMemorySize, G_SMEM);
    cudaFuncSetAttribute(attn_wmma, cudaFuncAttributeMaxDynamicSharedMemorySize, ATT_SMEM);

    // 0) fp32 -> fp16 converts
    f2h<<<4096, 256>>>(x,    (__half*)p_xh,    KM * KD);
    f2h<<<1024, 256>>>(Wqkv, (__half*)p_wqkvh, 1024 * 3072);
    f2h<<<512,  256>>>(Wo,   (__half*)p_woh,   1024 * 1024);

    // 1) QKV projection (fp16 out): 2 n-tiles per CTA
    gemm_2t<true><<<dim3(3072 / 256, KM / 128), 256, G_SMEM>>>(
        (const __half*)p_xh, (const __half*)p_wqkvh, bqkv, p_qkvh, 3072, 1024);

    // 2) WMMA sliding-window attention -> g_attnh
    attn_wmma<<<dim3(KS / 64, KH, KB), 256, ATT_SMEM>>>();

    // 3) Output projection (fp32 out): 2 n-tiles per CTA
    gemm_2t<false><<<dim3(1024 / 256, KM / 128), 256, G_SMEM>>>(
        (const __half*)p_attnh, (const __half*)p_woh, bo, out, 1024, 1024);
}

// round 15
// speedup vs baseline: 1.1065x; 1.1065x over previous
#include <cuda_runtime.h>
#include <cuda_fp16.h>
#include <mma.h>
#include <math_constants.h>
#include <cstdint>
#include <cstddef>

using namespace nvcuda;

// Problem constants
#define KB 8
#define KS 4096
#define KH 16
#define KD 1024
#define KM 32768      // B*S
#define KW 16

// Device scratch (allocation-free rules)
__device__ __align__(256) __half g_qkvh [(size_t)KM * 3072];  // fp16 QKV (+bias)
__device__ __align__(256) __half g_xh   [(size_t)KM * KD];    // x in fp16
__device__ __align__(256) __half g_attnh[(size_t)KM * KD];    // attention out fp16
__device__ __align__(256) __half g_wqkvh[1024 * 3072];        // Wqkv fp16 [K][N]
__device__ __align__(256) __half g_woh  [1024 * 1024];        // Wo   fp16 [K][N]

// ---------------------------------------------------------------------------
// PTX helpers
// ---------------------------------------------------------------------------
__device__ __forceinline__ uint32_t smem_u32(const void* p) {
    return (uint32_t)__cvta_generic_to_shared((void*)p);
}
__device__ __forceinline__ void cp_async16(uint32_t dst, const void* src) {
    asm volatile("cp.async.cg.shared.global [%0], [%1], 16;\n" :: "r"(dst), "l"(src) : "memory");
}
__device__ __forceinline__ void cp_commit() { asm volatile("cp.async.commit_group;\n" ::: "memory"); }
__device__ __forceinline__ void cp_wait0()  { asm volatile("cp.async.wait_group 0;\n" ::: "memory"); }
__device__ __forceinline__ void cp_wait1()  { asm volatile("cp.async.wait_group 1;\n" ::: "memory"); }

__device__ __forceinline__ void ldsm_x4(uint32_t& r0, uint32_t& r1, uint32_t& r2, uint32_t& r3,
                                        uint32_t addr) {
    asm volatile("ldmatrix.sync.aligned.m8n8.x4.shared.b16 {%0,%1,%2,%3}, [%4];"
                 : "=r"(r0), "=r"(r1), "=r"(r2), "=r"(r3) : "r"(addr));
}
__device__ __forceinline__ void ldsm_x4_t(uint32_t& r0, uint32_t& r1, uint32_t& r2, uint32_t& r3,
                                          uint32_t addr) {
    asm volatile("ldmatrix.sync.aligned.m8n8.x4.trans.shared.b16 {%0,%1,%2,%3}, [%4];"
                 : "=r"(r0), "=r"(r1), "=r"(r2), "=r"(r3) : "r"(addr));
}
__device__ __forceinline__ void mma16816(float* d, const uint32_t* a, uint32_t b0, uint32_t b1) {
    asm volatile("mma.sync.aligned.m16n8k16.row.col.f32.f16.f16.f32 "
                 "{%0,%1,%2,%3}, {%4,%5,%6,%7}, {%8,%9}, {%0,%1,%2,%3};"
                 : "+f"(d[0]), "+f"(d[1]), "+f"(d[2]), "+f"(d[3])
                 : "r"(a[0]), "r"(a[1]), "r"(a[2]), "r"(a[3]), "r"(b0), "r"(b1));
}
__device__ __forceinline__ uint32_t pack_h2(float a, float b) {
    __half2 h = __floats2half2_rn(a, b);
    return *reinterpret_cast<uint32_t*>(&h);
}

// ---------------------------------------------------------------------------
// fp32 -> fp16 convert
// ---------------------------------------------------------------------------
__global__ void f2h(const float* __restrict__ in, __half* __restrict__ out, int n)
{
    int i = (blockIdx.x * blockDim.x + threadIdx.x) * 4;
    const int stride = gridDim.x * blockDim.x * 4;
    for (; i < n; i += stride) {
        float4 v = *(const float4*)(in + i);
        __half2 h0 = __floats2half2_rn(v.x, v.y);
        __half2 h1 = __floats2half2_rn(v.z, v.w);
        uint2 u;
        u.x = *reinterpret_cast<uint32_t*>(&h0);
        u.y = *reinterpret_cast<uint32_t*>(&h1);
        *(uint2*)(out + i) = u;
    }
}

// ---------------------------------------------------------------------------
// Common stage geometry (BK=64)
// ---------------------------------------------------------------------------
#define G_LDA 72
#define G_LDB 136
#define G_ASZ (128 * G_LDA * 2)
#define G_STG (G_ASZ + 64 * G_LDB * 2)
#define G_SMEM (3 * G_STG)

// ---------------------------------------------------------------------------
// GEMM variant A (round 11): 256 thr, 8 warps 2x4, warp tile 64x32. (GEMM2)
// ---------------------------------------------------------------------------
template<bool HALF_OUT>
__global__ __launch_bounds__(256, 2)
void gemm_k64(const __half* __restrict__ A, const __half* __restrict__ Bw,
              const float* __restrict__ bias, void* __restrict__ Cv,
              int N, int K)
{
    extern __shared__ __align__(16) char sm[];
    const uint32_t sbase = smem_u32(sm);
    const int tid    = threadIdx.x;
    const int warpId = tid >> 5;
    const int lane   = tid & 31;
    const int warpM  = warpId & 1;
    const int warpN  = warpId >> 1;
    const int m0 = blockIdx.y * 128;
    const int n0 = blockIdx.x * 128;
    const int nT = K >> 6;

    auto fill = [&](int t, int slot) {
        const int k0 = t << 6;
        const uint32_t sb = sbase + (uint32_t)slot * G_STG;
#pragma unroll
        for (int u = 0; u < 4; u++) {
            int i = tid + u * 256;
            int r = i >> 3, c = (i & 7) * 8;
            cp_async16(sb + r * (G_LDA * 2) + c * 2, A + (size_t)(m0 + r) * K + k0 + c);
        }
#pragma unroll
        for (int u = 0; u < 4; u++) {
            int i = tid + u * 256;
            int r = i >> 4, c = (i & 15) * 8;
            cp_async16(sb + G_ASZ + r * (G_LDB * 2) + c * 2,
                       Bw + (size_t)(k0 + r) * N + n0 + c);
        }
    };

    fill(0, 0); cp_commit();
    fill(1, 1); cp_commit();

    wmma::fragment<wmma::accumulator, 16, 16, 16, float> cf[4][2];
#pragma unroll
    for (int i = 0; i < 4; i++)
#pragma unroll
        for (int j = 0; j < 2; j++)
            wmma::fill_fragment(cf[i][j], 0.0f);

    for (int t = 0; t < nT; t++) {
        const int slot = t % 3;
        if (t + 1 < nT) cp_wait1(); else cp_wait0();
        __syncthreads();
        if (t + 2 < nT) { fill(t + 2, (t + 2) % 3); cp_commit(); }

        const __half* As_ = (const __half*)(sm + (size_t)slot * G_STG);
        const __half* Bs_ = (const __half*)(sm + (size_t)slot * G_STG + G_ASZ);
#pragma unroll
        for (int kk = 0; kk < 4; kk++) {
            wmma::fragment<wmma::matrix_b, 16, 16, 16, __half, wmma::row_major> bf[2];
#pragma unroll
            for (int j = 0; j < 2; j++)
                wmma::load_matrix_sync(bf[j], &Bs_[(kk * 16) * G_LDB + warpN * 32 + j * 16], G_LDB);
#pragma unroll
            for (int i = 0; i < 4; i++) {
                wmma::fragment<wmma::matrix_a, 16, 16, 16, __half, wmma::row_major> af;
                wmma::load_matrix_sync(af, &As_[(warpM * 64 + i * 16) * G_LDA + kk * 16], G_LDA);
#pragma unroll
                for (int j = 0; j < 2; j++)
                    wmma::mma_sync(cf[i][j], af, bf[j], cf[i][j]);
            }
        }
    }

    __syncthreads();

    float* stg = (float*)sm + warpId * 320;
    const int r  = lane >> 1;
    const int c8 = (lane & 1) * 8;
#pragma unroll
    for (int j = 0; j < 2; j++) {
        const float* bp = bias + n0 + warpN * 32 + j * 16 + c8;
        const float4 b0 = *(const float4*)bp;
        const float4 b1 = *(const float4*)(bp + 4);
#pragma unroll
        for (int i = 0; i < 4; i++) {
            wmma::store_matrix_sync(stg, cf[i][j], 20, wmma::mem_row_major);
            __syncwarp();
            const float* s = stg + r * 20 + c8;
            float v0 = s[0] + b0.x, v1 = s[1] + b0.y, v2 = s[2] + b0.z, v3 = s[3] + b0.w;
            float v4 = s[4] + b1.x, v5 = s[5] + b1.y, v6 = s[6] + b1.z, v7 = s[7] + b1.w;
            const size_t row = (size_t)(m0 + warpM * 64 + i * 16 + r);
            const int    col = n0 + warpN * 32 + j * 16 + c8;
            if (HALF_OUT) {
                __half2 h0 = __floats2half2_rn(v0, v1);
                __half2 h1 = __floats2half2_rn(v2, v3);
                __half2 h2 = __floats2half2_rn(v4, v5);
                __half2 h3 = __floats2half2_rn(v6, v7);
                uint4 u;
                u.x = *reinterpret_cast<uint32_t*>(&h0);
                u.y = *reinterpret_cast<uint32_t*>(&h1);
                u.z = *reinterpret_cast<uint32_t*>(&h2);
                u.w = *reinterpret_cast<uint32_t*>(&h3);
                *(uint4*)((__half*)Cv + row * N + col) = u;
            } else {
                *(float4*)((float*)Cv + row * N + col)     = make_float4(v0, v1, v2, v3);
                *(float4*)((float*)Cv + row * N + col + 4) = make_float4(v4, v5, v6, v7);
            }
            __syncwarp();
        }
    }
}

// ---------------------------------------------------------------------------
// GEMM variant B (round 13 best): 128 thr, 4 warps 2x2, warp tile 64x64. (GEMM1)
// ---------------------------------------------------------------------------
template<bool HALF_OUT>
__global__ __launch_bounds__(128, 2)
void gemm_w64(const __half* __restrict__ A, const __half* __restrict__ Bw,
              const float* __restrict__ bias, void* __restrict__ Cv,
              int N, int K)
{
    extern __shared__ __align__(16) char sm[];
    const uint32_t sbase = smem_u32(sm);
    const int tid    = threadIdx.x;
    const int warpId = tid >> 5;
    const int lane   = tid & 31;
    const int wm = warpId & 1;
    const int wn = warpId >> 1;
    const int m0 = blockIdx.y * 128;
    const int n0 = blockIdx.x * 128;
    const int nT = K >> 6;

    auto fill = [&](int t, int slot) {
        const int k0 = t << 6;
        const uint32_t sb = sbase + (uint32_t)slot * G_STG;
#pragma unroll
        for (int u = 0; u < 8; u++) {
            int i = tid + u * 128;
            int r = i >> 3, c = (i & 7) * 8;
            cp_async16(sb + r * (G_LDA * 2) + c * 2, A + (size_t)(m0 + r) * K + k0 + c);
        }
#pragma unroll
        for (int u = 0; u < 8; u++) {
            int i = tid + u * 128;
            int r = i >> 4, c = (i & 15) * 8;
            cp_async16(sb + G_ASZ + r * (G_LDB * 2) + c * 2,
                       Bw + (size_t)(k0 + r) * N + n0 + c);
        }
    };

    fill(0, 0); cp_commit();
    fill(1, 1); cp_commit();

    wmma::fragment<wmma::accumulator, 16, 16, 16, float> cf[4][4];
#pragma unroll
    for (int i = 0; i < 4; i++)
#pragma unroll
        for (int j = 0; j < 4; j++)
            wmma::fill_fragment(cf[i][j], 0.0f);

    for (int t = 0; t < nT; t++) {
        const int slot = t % 3;
        if (t + 1 < nT) cp_wait1(); else cp_wait0();
        __syncthreads();
        if (t + 2 < nT) { fill(t + 2, (t + 2) % 3); cp_commit(); }

        const __half* As_ = (const __half*)(sm + (size_t)slot * G_STG);
        const __half* Bs_ = (const __half*)(sm + (size_t)slot * G_STG + G_ASZ);
#pragma unroll
        for (int kk = 0; kk < 4; kk++) {
            wmma::fragment<wmma::matrix_b, 16, 16, 16, __half, wmma::row_major> bf[4];
#pragma unroll
            for (int j = 0; j < 4; j++)
                wmma::load_matrix_sync(bf[j], &Bs_[(kk * 16) * G_LDB + wn * 64 + j * 16], G_LDB);
#pragma unroll
            for (int i = 0; i < 4; i++) {
                wmma::fragment<wmma::matrix_a, 16, 16, 16, __half, wmma::row_major> af;
                wmma::load_matrix_sync(af, &As_[(wm * 64 + i * 16) * G_LDA + kk * 16], G_LDA);
#pragma unroll
                for (int j = 0; j < 4; j++)
                    wmma::mma_sync(cf[i][j], af, bf[j], cf[i][j]);
            }
        }
    }

    __syncthreads();

    float* stg = (float*)sm + warpId * 320;
    const int r  = lane >> 1;
    const int c8 = (lane & 1) * 8;
#pragma unroll
    for (int j = 0; j < 4; j++) {
        const float* bp = bias + n0 + wn * 64 + j * 16 + c8;
        const float4 b0 = *(const float4*)bp;
        const float4 b1 = *(const float4*)(bp + 4);
#pragma unroll
        for (int i = 0; i < 4; i++) {
            wmma::store_matrix_sync(stg, cf[i][j], 20, wmma::mem_row_major);
            __syncwarp();
            const float* s = stg + r * 20 + c8;
            float v0 = s[0] + b0.x, v1 = s[1] + b0.y, v2 = s[2] + b0.z, v3 = s[3] + b0.w;
            float v4 = s[4] + b1.x, v5 = s[5] + b1.y, v6 = s[6] + b1.z, v7 = s[7] + b1.w;
            const size_t row = (size_t)(m0 + wm * 64 + i * 16 + r);
            const int    col = n0 + wn * 64 + j * 16 + c8;
            if (HALF_OUT) {
                __half2 h0 = __floats2half2_rn(v0, v1);
                __half2 h1 = __floats2half2_rn(v2, v3);
                __half2 h2 = __floats2half2_rn(v4, v5);
                __half2 h3 = __floats2half2_rn(v6, v7);
                uint4 u;
                u.x = *reinterpret_cast<uint32_t*>(&h0);
                u.y = *reinterpret_cast<uint32_t*>(&h1);
                u.z = *reinterpret_cast<uint32_t*>(&h2);
                u.w = *reinterpret_cast<uint32_t*>(&h3);
                *(uint4*)((__half*)Cv + row * N + col) = u;
            } else {
                *(float4*)((float*)Cv + row * N + col)     = make_float4(v0, v1, v2, v3);
                *(float4*)((float*)Cv + row * N + col + 4) = make_float4(v4, v5, v6, v7);
            }
            __syncwarp();
        }
    }
}

// ---------------------------------------------------------------------------
// FA2-style sliding-window attention with raw mma.sync, register softmax.
// Block = 64 queries x (b,h), 128 threads (4 warps). Keys s0-16..s0+79.
// Warp w: rows 16w..16w+15. S (16x96) in regs; masked softmax via shfl in
// the 4-lane row groups; P converted in-register to A-fragments for P@V.
// smem: Q 64x72, K 96x72, V 96x72 halves (static, 36.9KB). ONE syncthreads.
// ---------------------------------------------------------------------------
__global__ __launch_bounds__(128)
void attn_fa()
{
    __shared__ __half Qh[64 * 72];
    __shared__ __half Kh[96 * 72];
    __shared__ __half Vh[96 * 72];

    const int b  = blockIdx.z;
    const int h  = blockIdx.y;
    const int s0 = blockIdx.x * 64;
    const int tid  = threadIdx.x;
    const int w    = tid >> 5;
    const int lane = tid & 31;
    const int wr   = w * 16;

    // ---- load Q (64x64), K,V (96x64) fp16 tiles ----
    const __half* qbase = g_qkvh + (size_t)(b * KS) * 3072 + h * 192;
#pragma unroll
    for (int u = 0; u < 4; u++) {
        int i = tid + u * 128;
        int r = i >> 3, c = (i & 7) * 8;
        *(uint4*)(Qh + r * 72 + c) = *(const uint4*)(qbase + (size_t)(s0 + r) * 3072 + c);
    }
#pragma unroll
    for (int u = 0; u < 6; u++) {
        int i = tid + u * 128;
        int r = i >> 3, c = (i & 7) * 8;
        int key = s0 - KW + r;
        key = key < 0 ? 0 : (key >= KS ? KS - 1 : key);
        *(uint4*)(Kh + r * 72 + c) = *(const uint4*)(qbase + (size_t)key * 3072 + 64 + c);
    }
#pragma unroll
    for (int u = 0; u < 6; u++) {
        int i = tid + u * 128;
        int r = i >> 3, c = (i & 7) * 8;
        int key = s0 - KW + r;
        key = key < 0 ? 0 : (key >= KS ? KS - 1 : key);
        *(uint4*)(Vh + r * 72 + c) = *(const uint4*)(qbase + (size_t)key * 3072 + 128 + c);
    }
    __syncthreads();

    const uint32_t qs = smem_u32(Qh);
    const uint32_t ks = smem_u32(Kh);
    const uint32_t vs = smem_u32(Vh);
    const int li = lane & 7;        // within-group row
    const int lg = lane >> 3;       // ldmatrix tile group 0..3
    const int lr = lane >> 2;       // acc row 0..7
    const int lc = lane & 3;        // acc col pair 0..3

    // ---- Q A-fragments: af[kt][0..3], kt = k-chunk of 16 ----
    uint32_t af[4][4];
#pragma unroll
    for (int kt = 0; kt < 4; kt++) {
        int row = wr + (lg & 1) * 8 + li;
        int col = kt * 16 + (lg >> 1) * 8;
        ldsm_x4(af[kt][0], af[kt][1], af[kt][2], af[kt][3],
                qs + (uint32_t)(row * 72 + col) * 2);
    }

    // ---- S = Q @ K^T : 12 n-atoms (8 keys each) ----
    float sacc[12][4];
#pragma unroll
    for (int na = 0; na < 12; na++)
#pragma unroll
        for (int e = 0; e < 4; e++) sacc[na][e] = 0.0f;

#pragma unroll
    for (int nn = 0; nn < 6; nn++) {
        const int n0 = nn * 16;
#pragma unroll
        for (int kt = 0; kt < 4; kt++) {
            uint32_t b0, b1, b2, b3;
            int row = n0 + (lg >> 1) * 8 + li;
            int col = kt * 16 + (lg & 1) * 8;
            ldsm_x4(b0, b1, b2, b3, ks + (uint32_t)(row * 72 + col) * 2);
            mma16816(sacc[2 * nn],     af[kt], b0, b1);
            mma16816(sacc[2 * nn + 1], af[kt], b2, b3);
        }
    }

    // ---- masked softmax in fragments ----
    const int rA = wr + lr;         // this lane's rows: rA, rA+8
    float mx0 = -1e30f, mx1 = -1e30f;
#pragma unroll
    for (int na = 0; na < 12; na++) {
        const int j0 = na * 8 + lc * 2;
        const int j1 = j0 + 1;
        const int k0g = s0 - KW + j0, k1g = k0g + 1;
        // row rA
        bool v00 = (j0 >= rA) && (j0 <= rA + 32) && (k0g >= 0) && (k0g < KS);
        bool v01 = (j1 >= rA) && (j1 <= rA + 32) && (k1g >= 0) && (k1g < KS);
        // row rA+8
        bool v10 = (j0 >= rA + 8) && (j0 <= rA + 40) && (k0g >= 0) && (k0g < KS);
        bool v11 = (j1 >= rA + 8) && (j1 <= rA + 40) && (k1g >= 0) && (k1g < KS);
        sacc[na][0] = v00 ? sacc[na][0] : -1e30f;
        sacc[na][1] = v01 ? sacc[na][1] : -1e30f;
        sacc[na][2] = v10 ? sacc[na][2] : -1e30f;
        sacc[na][3] = v11 ? sacc[na][3] : -1e30f;
        mx0 = fmaxf(mx0, fmaxf(sacc[na][0], sacc[na][1]));
        mx1 = fmaxf(mx1, fmaxf(sacc[na][2], sacc[na][3]));
    }
    mx0 = fmaxf(mx0, __shfl_xor_sync(0xffffffffu, mx0, 1));
    mx0 = fmaxf(mx0, __shfl_xor_sync(0xffffffffu, mx0, 2));
    mx1 = fmaxf(mx1, __shfl_xor_sync(0xffffffffu, mx1, 1));
    mx1 = fmaxf(mx1, __shfl_xor_sync(0xffffffffu, mx1, 2));

    float sum0 = 0.0f, sum1 = 0.0f;
#pragma unroll
    for (int na = 0; na < 12; na++) {
        float e0 = __expf(0.125f * (sacc[na][0] - mx0));
        float e1 = __expf(0.125f * (sacc[na][1] - mx0));
        float e2 = __expf(0.125f * (sacc[na][2] - mx1));
        float e3 = __expf(0.125f * (sacc[na][3] - mx1));
        sacc[na][0] = e0; sacc[na][1] = e1; sacc[na][2] = e2; sacc[na][3] = e3;
        sum0 += e0 + e1; sum1 += e2 + e3;
    }
    sum0 += __shfl_xor_sync(0xffffffffu, sum0, 1);
    sum0 += __shfl_xor_sync(0xffffffffu, sum0, 2);
    sum1 += __shfl_xor_sync(0xffffffffu, sum1, 1);
    sum1 += __shfl_xor_sync(0xffffffffu, sum1, 2);
    const float inv0 = 1.0f / sum0;
    const float inv1 = 1.0f / sum1;
#pragma unroll
    for (int na = 0; na < 12; na++) {
        sacc[na][0] *= inv0; sacc[na][1] *= inv0;
        sacc[na][2] *= inv1; sacc[na][3] *= inv1;
    }

    // ---- O = P @ V : P from S fragments (C-layout == A-layout identity) ----
    float oacc[8][4];
#pragma unroll
    for (int na = 0; na < 8; na++)
#pragma unroll
        for (int e = 0; e < 4; e++) oacc[na][e] = 0.0f;

#pragma unroll
    for (int kt = 0; kt < 6; kt++) {
        uint32_t a[4];
        a[0] = pack_h2(sacc[2 * kt][0],     sacc[2 * kt][1]);
        a[1] = pack_h2(sacc[2 * kt][2],     sacc[2 * kt][3]);
        a[2] = pack_h2(sacc[2 * kt + 1][0], sacc[2 * kt + 1][1]);
        a[3] = pack_h2(sacc[2 * kt + 1][2], sacc[2 * kt + 1][3]);
        const int k0 = kt * 16;
#pragma unroll
        for (int np = 0; np < 4; np++) {
            const int n0 = np * 16;
            uint32_t b0, b1, b2, b3;
            int row = k0 + (lg & 1) * 8 + li;
            int col = n0 + (lg >> 1) * 8;
            ldsm_x4_t(b0, b1, b2, b3, vs + (uint32_t)(row * 72 + col) * 2);
            mma16816(oacc[2 * np],     a, b0, b1);
            mma16816(oacc[2 * np + 1], a, b2, b3);
        }
    }

    // ---- store fp16 output (half2 per element pair) ----
    __half* op = g_attnh + (size_t)(b * KS + s0) * KD + h * 64;
#pragma unroll
    for (int na = 0; na < 8; na++) {
        const int col = na * 8 + lc * 2;
        __half2 h0 = __floats2half2_rn(oacc[na][0], oacc[na][1]);
        __half2 h1 = __floats2half2_rn(oacc[na][2], oacc[na][3]);
        *(__half2*)(op + (size_t)rA * KD + col)       = h0;
        *(__half2*)(op + (size_t)(rA + 8) * KD + col) = h1;
    }
}

// ---------------------------------------------------------------------------
extern "C" void kernel_launch(void* const* d_in, const int* in_sizes, int n_in,
                              void* d_out, int out_size)
{
    const float* x    = (const float*)d_in[0];
    const float* Wqkv = (const float*)d_in[1];
    const float* bqkv = (const float*)d_in[2];
    const float* Wo   = (const float*)d_in[3];
    const float* bo   = (const float*)d_in[4];
    float* out = (float*)d_out;

    void *p_qkvh, *p_xh, *p_attnh, *p_wqkvh, *p_woh;
    cudaGetSymbolAddress(&p_qkvh,  g_qkvh);
    cudaGetSymbolAddress(&p_xh,    g_xh);
    cudaGetSymbolAddress(&p_attnh, g_attnh);
    cudaGetSymbolAddress(&p_wqkvh, g_wqkvh);
    cudaGetSymbolAddress(&p_woh,   g_woh);

    cudaFuncSetAttribute(gemm_w64<true>,  cudaFuncAttributeMaxDynamicSharedMemorySize, G_SMEM);
    cudaFuncSetAttribute(gemm_k64<false>, cudaFuncAttributeMaxDynamicSharedMemorySize, G_SMEM);

    // 0) fp32 -> fp16 converts
    f2h<<<4096, 256>>>(x,    (__half*)p_xh,    KM * KD);
    f2h<<<1024, 256>>>(Wqkv, (__half*)p_wqkvh, 1024 * 3072);
    f2h<<<512,  256>>>(Wo,   (__half*)p_woh,   1024 * 1024);

    // 1) QKV projection (fp16 out): round-13 best geometry
    gemm_w64<true><<<dim3(3072 / 128, KM / 128), 128, G_SMEM>>>(
        (const __half*)p_xh, (const __half*)p_wqkvh, bqkv, p_qkvh, 3072, 1024);

    // 2) FA2-style sliding-window attention -> g_attnh
    attn_fa<<<dim3(KS / 64, KH, KB), 128>>>();

    // 3) Output projection (fp32 out): round-11 geometry
    gemm_k64<false><<<dim3(1024 / 128, KM / 128), 256, G_SMEM>>>(
        (const __half*)p_attnh, (const __half*)p_woh, bo, out, 1024, 1024);
}

// round 16
// speedup vs baseline: 1.1330x; 1.0239x over previous
#include <cuda_runtime.h>
#include <cuda_fp16.h>
#include <mma.h>
#include <math_constants.h>
#include <cstdint>
#include <cstddef>

using namespace nvcuda;

// Problem constants
#define KB 8
#define KS 4096
#define KH 16
#define KD 1024
#define KM 32768      // B*S
#define KW 16

// Device scratch (allocation-free rules)
__device__ __align__(256) __half g_qkvh [(size_t)KM * 3072];  // fp16 QKV (+bias)
__device__ __align__(256) __half g_xh   [(size_t)KM * KD];    // x in fp16
__device__ __align__(256) __half g_attnh[(size_t)KM * KD];    // attention out fp16
__device__ __align__(256) __half g_wqkvh[1024 * 3072];        // Wqkv fp16 [K][N]
__device__ __align__(256) __half g_woh  [1024 * 1024];        // Wo   fp16 [K][N]

// ---------------------------------------------------------------------------
// PTX helpers
// ---------------------------------------------------------------------------
__device__ __forceinline__ uint32_t smem_u32(const void* p) {
    return (uint32_t)__cvta_generic_to_shared((void*)p);
}
__device__ __forceinline__ void cp_async16(uint32_t dst, const void* src) {
    asm volatile("cp.async.cg.shared.global [%0], [%1], 16;\n" :: "r"(dst), "l"(src) : "memory");
}
__device__ __forceinline__ void cp_commit() { asm volatile("cp.async.commit_group;\n" ::: "memory"); }
__device__ __forceinline__ void cp_wait0()  { asm volatile("cp.async.wait_group 0;\n" ::: "memory"); }
__device__ __forceinline__ void cp_wait1()  { asm volatile("cp.async.wait_group 1;\n" ::: "memory"); }

__device__ __forceinline__ void ldsm_x4(uint32_t& r0, uint32_t& r1, uint32_t& r2, uint32_t& r3,
                                        uint32_t addr) {
    asm volatile("ldmatrix.sync.aligned.m8n8.x4.shared.b16 {%0,%1,%2,%3}, [%4];"
                 : "=r"(r0), "=r"(r1), "=r"(r2), "=r"(r3) : "r"(addr));
}
__device__ __forceinline__ void ldsm_x4_t(uint32_t& r0, uint32_t& r1, uint32_t& r2, uint32_t& r3,
                                          uint32_t addr) {
    asm volatile("ldmatrix.sync.aligned.m8n8.x4.trans.shared.b16 {%0,%1,%2,%3}, [%4];"
                 : "=r"(r0), "=r"(r1), "=r"(r2), "=r"(r3) : "r"(addr));
}
__device__ __forceinline__ void mma16816(float* d, const uint32_t* a, uint32_t b0, uint32_t b1) {
    asm volatile("mma.sync.aligned.m16n8k16.row.col.f32.f16.f16.f32 "
                 "{%0,%1,%2,%3}, {%4,%5,%6,%7}, {%8,%9}, {%0,%1,%2,%3};"
                 : "+f"(d[0]), "+f"(d[1]), "+f"(d[2]), "+f"(d[3])
                 : "r"(a[0]), "r"(a[1]), "r"(a[2]), "r"(a[3]), "r"(b0), "r"(b1));
}
__device__ __forceinline__ uint32_t pack_h2(float a, float b) {
    __half2 h = __floats2half2_rn(a, b);
    return *reinterpret_cast<uint32_t*>(&h);
}

// ---------------------------------------------------------------------------
// fp32 -> fp16 convert
// ---------------------------------------------------------------------------
__global__ void f2h(const float* __restrict__ in, __half* __restrict__ out, int n)
{
    int i = (blockIdx.x * blockDim.x + threadIdx.x) * 4;
    const int stride = gridDim.x * blockDim.x * 4;
    for (; i < n; i += stride) {
        float4 v = *(const float4*)(in + i);
        __half2 h0 = __floats2half2_rn(v.x, v.y);
        __half2 h1 = __floats2half2_rn(v.z, v.w);
        uint2 u;
        u.x = *reinterpret_cast<uint32_t*>(&h0);
        u.y = *reinterpret_cast<uint32_t*>(&h1);
        *(uint2*)(out + i) = u;
    }
}

// ---------------------------------------------------------------------------
// Common stage geometry (BK=64)
// ---------------------------------------------------------------------------
#define G_LDA 72
#define G_LDB 136
#define G_ASZ (128 * G_LDA * 2)
#define G_STG (G_ASZ + 64 * G_LDB * 2)
#define G_SMEM (3 * G_STG)

// ---------------------------------------------------------------------------
// GEMM variant A (round 11): 256 thr, 8 warps 2x4, warp tile 64x32. (GEMM2)
// ---------------------------------------------------------------------------
template<bool HALF_OUT>
__global__ __launch_bounds__(256, 2)
void gemm_k64(const __half* __restrict__ A, const __half* __restrict__ Bw,
              const float* __restrict__ bias, void* __restrict__ Cv,
              int N, int K)
{
    extern __shared__ __align__(16) char sm[];
    const uint32_t sbase = smem_u32(sm);
    const int tid    = threadIdx.x;
    const int warpId = tid >> 5;
    const int lane   = tid & 31;
    const int warpM  = warpId & 1;
    const int warpN  = warpId >> 1;
    const int m0 = blockIdx.y * 128;
    const int n0 = blockIdx.x * 128;
    const int nT = K >> 6;

    auto fill = [&](int t, int slot) {
        const int k0 = t << 6;
        const uint32_t sb = sbase + (uint32_t)slot * G_STG;
#pragma unroll
        for (int u = 0; u < 4; u++) {
            int i = tid + u * 256;
            int r = i >> 3, c = (i & 7) * 8;
            cp_async16(sb + r * (G_LDA * 2) + c * 2, A + (size_t)(m0 + r) * K + k0 + c);
        }
#pragma unroll
        for (int u = 0; u < 4; u++) {
            int i = tid + u * 256;
            int r = i >> 4, c = (i & 15) * 8;
            cp_async16(sb + G_ASZ + r * (G_LDB * 2) + c * 2,
                       Bw + (size_t)(k0 + r) * N + n0 + c);
        }
    };

    fill(0, 0); cp_commit();
    fill(1, 1); cp_commit();

    wmma::fragment<wmma::accumulator, 16, 16, 16, float> cf[4][2];
#pragma unroll
    for (int i = 0; i < 4; i++)
#pragma unroll
        for (int j = 0; j < 2; j++)
            wmma::fill_fragment(cf[i][j], 0.0f);

    for (int t = 0; t < nT; t++) {
        const int slot = t % 3;
        if (t + 1 < nT) cp_wait1(); else cp_wait0();
        __syncthreads();
        if (t + 2 < nT) { fill(t + 2, (t + 2) % 3); cp_commit(); }

        const __half* As_ = (const __half*)(sm + (size_t)slot * G_STG);
        const __half* Bs_ = (const __half*)(sm + (size_t)slot * G_STG + G_ASZ);
#pragma unroll
        for (int kk = 0; kk < 4; kk++) {
            wmma::fragment<wmma::matrix_b, 16, 16, 16, __half, wmma::row_major> bf[2];
#pragma unroll
            for (int j = 0; j < 2; j++)
                wmma::load_matrix_sync(bf[j], &Bs_[(kk * 16) * G_LDB + warpN * 32 + j * 16], G_LDB);
#pragma unroll
            for (int i = 0; i < 4; i++) {
                wmma::fragment<wmma::matrix_a, 16, 16, 16, __half, wmma::row_major> af;
                wmma::load_matrix_sync(af, &As_[(warpM * 64 + i * 16) * G_LDA + kk * 16], G_LDA);
#pragma unroll
                for (int j = 0; j < 2; j++)
                    wmma::mma_sync(cf[i][j], af, bf[j], cf[i][j]);
            }
        }
    }

    __syncthreads();

    float* stg = (float*)sm + warpId * 320;
    const int r  = lane >> 1;
    const int c8 = (lane & 1) * 8;
#pragma unroll
    for (int j = 0; j < 2; j++) {
        const float* bp = bias + n0 + warpN * 32 + j * 16 + c8;
        const float4 b0 = *(const float4*)bp;
        const float4 b1 = *(const float4*)(bp + 4);
#pragma unroll
        for (int i = 0; i < 4; i++) {
            wmma::store_matrix_sync(stg, cf[i][j], 20, wmma::mem_row_major);
            __syncwarp();
            const float* s = stg + r * 20 + c8;
            float v0 = s[0] + b0.x, v1 = s[1] + b0.y, v2 = s[2] + b0.z, v3 = s[3] + b0.w;
            float v4 = s[4] + b1.x, v5 = s[5] + b1.y, v6 = s[6] + b1.z, v7 = s[7] + b1.w;
            const size_t row = (size_t)(m0 + warpM * 64 + i * 16 + r);
            const int    col = n0 + warpN * 32 + j * 16 + c8;
            if (HALF_OUT) {
                __half2 h0 = __floats2half2_rn(v0, v1);
                __half2 h1 = __floats2half2_rn(v2, v3);
                __half2 h2 = __floats2half2_rn(v4, v5);
                __half2 h3 = __floats2half2_rn(v6, v7);
                uint4 u;
                u.x = *reinterpret_cast<uint32_t*>(&h0);
                u.y = *reinterpret_cast<uint32_t*>(&h1);
                u.z = *reinterpret_cast<uint32_t*>(&h2);
                u.w = *reinterpret_cast<uint32_t*>(&h3);
                *(uint4*)((__half*)Cv + row * N + col) = u;
            } else {
                *(float4*)((float*)Cv + row * N + col)     = make_float4(v0, v1, v2, v3);
                *(float4*)((float*)Cv + row * N + col + 4) = make_float4(v4, v5, v6, v7);
            }
            __syncwarp();
        }
    }
}

// ---------------------------------------------------------------------------
// GEMM variant B (round 13 best): 128 thr, 4 warps 2x2, warp tile 64x64. (GEMM1)
// ---------------------------------------------------------------------------
template<bool HALF_OUT>
__global__ __launch_bounds__(128, 2)
void gemm_w64(const __half* __restrict__ A, const __half* __restrict__ Bw,
              const float* __restrict__ bias, void* __restrict__ Cv,
              int N, int K)
{
    extern __shared__ __align__(16) char sm[];
    const uint32_t sbase = smem_u32(sm);
    const int tid    = threadIdx.x;
    const int warpId = tid >> 5;
    const int lane   = tid & 31;
    const int wm = warpId & 1;
    const int wn = warpId >> 1;
    const int m0 = blockIdx.y * 128;
    const int n0 = blockIdx.x * 128;
    const int nT = K >> 6;

    auto fill = [&](int t, int slot) {
        const int k0 = t << 6;
        const uint32_t sb = sbase + (uint32_t)slot * G_STG;
#pragma unroll
        for (int u = 0; u < 8; u++) {
            int i = tid + u * 128;
            int r = i >> 3, c = (i & 7) * 8;
            cp_async16(sb + r * (G_LDA * 2) + c * 2, A + (size_t)(m0 + r) * K + k0 + c);
        }
#pragma unroll
        for (int u = 0; u < 8; u++) {
            int i = tid + u * 128;
            int r = i >> 4, c = (i & 15) * 8;
            cp_async16(sb + G_ASZ + r * (G_LDB * 2) + c * 2,
                       Bw + (size_t)(k0 + r) * N + n0 + c);
        }
    };

    fill(0, 0); cp_commit();
    fill(1, 1); cp_commit();

    wmma::fragment<wmma::accumulator, 16, 16, 16, float> cf[4][4];
#pragma unroll
    for (int i = 0; i < 4; i++)
#pragma unroll
        for (int j = 0; j < 4; j++)
            wmma::fill_fragment(cf[i][j], 0.0f);

    for (int t = 0; t < nT; t++) {
        const int slot = t % 3;
        if (t + 1 < nT) cp_wait1(); else cp_wait0();
        __syncthreads();
        if (t + 2 < nT) { fill(t + 2, (t + 2) % 3); cp_commit(); }

        const __half* As_ = (const __half*)(sm + (size_t)slot * G_STG);
        const __half* Bs_ = (const __half*)(sm + (size_t)slot * G_STG + G_ASZ);
#pragma unroll
        for (int kk = 0; kk < 4; kk++) {
            wmma::fragment<wmma::matrix_b, 16, 16, 16, __half, wmma::row_major> bf[4];
#pragma unroll
            for (int j = 0; j < 4; j++)
                wmma::load_matrix_sync(bf[j], &Bs_[(kk * 16) * G_LDB + wn * 64 + j * 16], G_LDB);
#pragma unroll
            for (int i = 0; i < 4; i++) {
                wmma::fragment<wmma::matrix_a, 16, 16, 16, __half, wmma::row_major> af;
                wmma::load_matrix_sync(af, &As_[(wm * 64 + i * 16) * G_LDA + kk * 16], G_LDA);
#pragma unroll
                for (int j = 0; j < 4; j++)
                    wmma::mma_sync(cf[i][j], af, bf[j], cf[i][j]);
            }
        }
    }

    __syncthreads();

    float* stg = (float*)sm + warpId * 320;
    const int r  = lane >> 1;
    const int c8 = (lane & 1) * 8;
#pragma unroll
    for (int j = 0; j < 4; j++) {
        const float* bp = bias + n0 + wn * 64 + j * 16 + c8;
        const float4 b0 = *(const float4*)bp;
        const float4 b1 = *(const float4*)(bp + 4);
#pragma unroll
        for (int i = 0; i < 4; i++) {
            wmma::store_matrix_sync(stg, cf[i][j], 20, wmma::mem_row_major);
            __syncwarp();
            const float* s = stg + r * 20 + c8;
            float v0 = s[0] + b0.x, v1 = s[1] + b0.y, v2 = s[2] + b0.z, v3 = s[3] + b0.w;
            float v4 = s[4] + b1.x, v5 = s[5] + b1.y, v6 = s[6] + b1.z, v7 = s[7] + b1.w;
            const size_t row = (size_t)(m0 + wm * 64 + i * 16 + r);
            const int    col = n0 + wn * 64 + j * 16 + c8;
            if (HALF_OUT) {
                __half2 h0 = __floats2half2_rn(v0, v1);
                __half2 h1 = __floats2half2_rn(v2, v3);
                __half2 h2 = __floats2half2_rn(v4, v5);
                __half2 h3 = __floats2half2_rn(v6, v7);
                uint4 u;
                u.x = *reinterpret_cast<uint32_t*>(&h0);
                u.y = *reinterpret_cast<uint32_t*>(&h1);
                u.z = *reinterpret_cast<uint32_t*>(&h2);
                u.w = *reinterpret_cast<uint32_t*>(&h3);
                *(uint4*)((__half*)Cv + row * N + col) = u;
            } else {
                *(float4*)((float*)Cv + row * N + col)     = make_float4(v0, v1, v2, v3);
                *(float4*)((float*)Cv + row * N + col + 4) = make_float4(v4, v5, v6, v7);
            }
            __syncwarp();
        }
    }
}

// ---------------------------------------------------------------------------
// Banded FA sliding-window attention. Block = 64 queries x (b,h), 128 thr.
// Keys s0-16..s0+79 in smem. Warp w (rows wr..wr+15) computes ONLY its
// valid 48-key band (local cols wr..wr+47): 12 S-mmas + 12 PV-mmas
// (was 24+24). Register softmax; ONE __syncthreads. cp.async tile loads.
// ---------------------------------------------------------------------------
__global__ __launch_bounds__(128)
void attn_fa()
{
    __shared__ __half Qh[64 * 72];
    __shared__ __half Kh[96 * 72];
    __shared__ __half Vh[96 * 72];

    const int b  = blockIdx.z;
    const int h  = blockIdx.y;
    const int s0 = blockIdx.x * 64;
    const int tid  = threadIdx.x;
    const int w    = tid >> 5;
    const int lane = tid & 31;
    const int wr   = w * 16;

    const uint32_t qs = smem_u32(Qh);
    const uint32_t ks = smem_u32(Kh);
    const uint32_t vs = smem_u32(Vh);

    // ---- cp.async tile loads: Q (64x64), K,V (96x64) fp16 ----
    const __half* qbase = g_qkvh + (size_t)(b * KS) * 3072 + h * 192;
#pragma unroll
    for (int u = 0; u < 4; u++) {
        int i = tid + u * 128;
        int r = i >> 3, c = (i & 7) * 8;
        cp_async16(qs + (uint32_t)(r * 72 + c) * 2,
                   qbase + (size_t)(s0 + r) * 3072 + c);
    }
#pragma unroll
    for (int u = 0; u < 6; u++) {
        int i = tid + u * 128;
        int r = i >> 3, c = (i & 7) * 8;
        int key = s0 - KW + r;
        key = key < 0 ? 0 : (key >= KS ? KS - 1 : key);   // clamp; masked later
        cp_async16(ks + (uint32_t)(r * 72 + c) * 2,
                   qbase + (size_t)key * 3072 + 64 + c);
    }
#pragma unroll
    for (int u = 0; u < 6; u++) {
        int i = tid + u * 128;
        int r = i >> 3, c = (i & 7) * 8;
        int key = s0 - KW + r;
        key = key < 0 ? 0 : (key >= KS ? KS - 1 : key);
        cp_async16(vs + (uint32_t)(r * 72 + c) * 2,
                   qbase + (size_t)key * 3072 + 128 + c);
    }
    cp_commit();
    cp_wait0();
    __syncthreads();

    const int li = lane & 7;        // within-group row
    const int lg = lane >> 3;       // ldmatrix tile group 0..3
    const int lr = lane >> 2;       // acc row 0..7
    const int lc = lane & 3;        // acc col pair 0..3

    // ---- Q A-fragments: af[kt][0..3], kt = k-chunk of 16 ----
    uint32_t af[4][4];
#pragma unroll
    for (int kt = 0; kt < 4; kt++) {
        int row = wr + (lg & 1) * 8 + li;
        int col = kt * 16 + (lg >> 1) * 8;
        ldsm_x4(af[kt][0], af[kt][1], af[kt][2], af[kt][3],
                qs + (uint32_t)(row * 72 + col) * 2);
    }

    // ---- S = Q @ K^T over the 48-key band [wr, wr+47]: 6 n-atoms ----
    float sacc[6][4];
#pragma unroll
    for (int na = 0; na < 6; na++)
#pragma unroll
        for (int e = 0; e < 4; e++) sacc[na][e] = 0.0f;

#pragma unroll
    for (int nn = 0; nn < 3; nn++) {
        const int n0 = wr + nn * 16;       // band-local K rows
#pragma unroll
        for (int kt = 0; kt < 4; kt++) {
            uint32_t b0, b1, b2, b3;
            int row = n0 + (lg >> 1) * 8 + li;
            int col = kt * 16 + (lg & 1) * 8;
            ldsm_x4(b0, b1, b2, b3, ks + (uint32_t)(row * 72 + col) * 2);
            mma16816(sacc[2 * nn],     af[kt], b0, b1);
            mma16816(sacc[2 * nn + 1], af[kt], b2, b3);
        }
    }

    // ---- masked softmax in fragments (rows rA, rA+8) ----
    const int rA = wr + lr;
    float mx0 = -1e30f, mx1 = -1e30f;
#pragma unroll
    for (int na = 0; na < 6; na++) {
        const int j0 = wr + na * 8 + lc * 2;   // band-local key col
        const int j1 = j0 + 1;
        const int k0g = s0 - KW + j0, k1g = k0g + 1;
        bool v00 = (j0 >= rA) && (j0 <= rA + 32) && (k0g >= 0) && (k0g < KS);
        bool v01 = (j1 >= rA) && (j1 <= rA + 32) && (k1g >= 0) && (k1g < KS);
        bool v10 = (j0 >= rA + 8) && (j0 <= rA + 40) && (k0g >= 0) && (k0g < KS);
        bool v11 = (j1 >= rA + 8) && (j1 <= rA + 40) && (k1g >= 0) && (k1g < KS);
        sacc[na][0] = v00 ? sacc[na][0] : -1e30f;
        sacc[na][1] = v01 ? sacc[na][1] : -1e30f;
        sacc[na][2] = v10 ? sacc[na][2] : -1e30f;
        sacc[na][3] = v11 ? sacc[na][3] : -1e30f;
        mx0 = fmaxf(mx0, fmaxf(sacc[na][0], sacc[na][1]));
        mx1 = fmaxf(mx1, fmaxf(sacc[na][2], sacc[na][3]));
    }
    mx0 = fmaxf(mx0, __shfl_xor_sync(0xffffffffu, mx0, 1));
    mx0 = fmaxf(mx0, __shfl_xor_sync(0xffffffffu, mx0, 2));
    mx1 = fmaxf(mx1, __shfl_xor_sync(0xffffffffu, mx1, 1));
    mx1 = fmaxf(mx1, __shfl_xor_sync(0xffffffffu, mx1, 2));

    float sum0 = 0.0f, sum1 = 0.0f;
#pragma unroll
    for (int na = 0; na < 6; na++) {
        float e0 = __expf(0.125f * (sacc[na][0] - mx0));
        float e1 = __expf(0.125f * (sacc[na][1] - mx0));
        float e2 = __expf(0.125f * (sacc[na][2] - mx1));
        float e3 = __expf(0.125f * (sacc[na][3] - mx1));
        sacc[na][0] = e0; sacc[na][1] = e1; sacc[na][2] = e2; sacc[na][3] = e3;
        sum0 += e0 + e1; sum1 += e2 + e3;
    }
    sum0 += __shfl_xor_sync(0xffffffffu, sum0, 1);
    sum0 += __shfl_xor_sync(0xffffffffu, sum0, 2);
    sum1 += __shfl_xor_sync(0xffffffffu, sum1, 1);
    sum1 += __shfl_xor_sync(0xffffffffu, sum1, 2);
    const float inv0 = 1.0f / sum0;
    const float inv1 = 1.0f / sum1;
#pragma unroll
    for (int na = 0; na < 6; na++) {
        sacc[na][0] *= inv0; sacc[na][1] *= inv0;
        sacc[na][2] *= inv1; sacc[na][3] *= inv1;
    }

    // ---- O = P @ V over the band: V rows wr+kt*16, kt=0..2 ----
    float oacc[8][4];
#pragma unroll
    for (int na = 0; na < 8; na++)
#pragma unroll
        for (int e = 0; e < 4; e++) oacc[na][e] = 0.0f;

#pragma unroll
    for (int kt = 0; kt < 3; kt++) {
        uint32_t a[4];
        a[0] = pack_h2(sacc[2 * kt][0],     sacc[2 * kt][1]);
        a[1] = pack_h2(sacc[2 * kt][2],     sacc[2 * kt][3]);
        a[2] = pack_h2(sacc[2 * kt + 1][0], sacc[2 * kt + 1][1]);
        a[3] = pack_h2(sacc[2 * kt + 1][2], sacc[2 * kt + 1][3]);
        const int k0 = wr + kt * 16;       // band-local V rows
#pragma unroll
        for (int np = 0; np < 4; np++) {
            const int n0 = np * 16;
            uint32_t b0, b1, b2, b3;
            int row = k0 + (lg & 1) * 8 + li;
            int col = n0 + (lg >> 1) * 8;
            ldsm_x4_t(b0, b1, b2, b3, vs + (uint32_t)(row * 72 + col) * 2);
            mma16816(oacc[2 * np],     a, b0, b1);
            mma16816(oacc[2 * np + 1], a, b2, b3);
        }
    }

    // ---- store fp16 output ----
    __half* op = g_attnh + (size_t)(b * KS + s0) * KD + h * 64;
#pragma unroll
    for (int na = 0; na < 8; na++) {
        const int col = na * 8 + lc * 2;
        __half2 h0 = __floats2half2_rn(oacc[na][0], oacc[na][1]);
        __half2 h1 = __floats2half2_rn(oacc[na][2], oacc[na][3]);
        *(__half2*)(op + (size_t)rA * KD + col)       = h0;
        *(__half2*)(op + (size_t)(rA + 8) * KD + col) = h1;
    }
}

// ---------------------------------------------------------------------------
extern "C" void kernel_launch(void* const* d_in, const int* in_sizes, int n_in,
                              void* d_out, int out_size)
{
    const float* x    = (const float*)d_in[0];
    const float* Wqkv = (const float*)d_in[1];
    const float* bqkv = (const float*)d_in[2];
    const float* Wo   = (const float*)d_in[3];
    const float* bo   = (const float*)d_in[4];
    float* out = (float*)d_out;

    void *p_qkvh, *p_xh, *p_attnh, *p_wqkvh, *p_woh;
    cudaGetSymbolAddress(&p_qkvh,  g_qkvh);
    cudaGetSymbolAddress(&p_xh,    g_xh);
    cudaGetSymbolAddress(&p_attnh, g_attnh);
    cudaGetSymbolAddress(&p_wqkvh, g_wqkvh);
    cudaGetSymbolAddress(&p_woh,   g_woh);

    cudaFuncSetAttribute(gemm_w64<true>,  cudaFuncAttributeMaxDynamicSharedMemorySize, G_SMEM);
    cudaFuncSetAttribute(gemm_k64<false>, cudaFuncAttributeMaxDynamicSharedMemorySize, G_SMEM);

    // 0) fp32 -> fp16 converts
    f2h<<<4096, 256>>>(x,    (__half*)p_xh,    KM * KD);
    f2h<<<1024, 256>>>(Wqkv, (__half*)p_wqkvh, 1024 * 3072);
    f2h<<<512,  256>>>(Wo,   (__half*)p_woh,   1024 * 1024);

    // 1) QKV projection (fp16 out): round-13 best geometry
    gemm_w64<true><<<dim3(3072 / 128, KM / 128), 128, G_SMEM>>>(
        (const __half*)p_xh, (const __half*)p_wqkvh, bqkv, p_qkvh, 3072, 1024);

    // 2) Banded FA sliding-window attention -> g_attnh
    attn_fa<<<dim3(KS / 64, KH, KB), 128>>>();

    // 3) Output projection (fp32 out): round-11 geometry
    gemm_k64<false><<<dim3(1024 / 128, KM / 128), 256, G_SMEM>>>(
        (const __half*)p_attnh, (const __half*)p_woh, bo, out, 1024, 1024);
}

// round 17
// speedup vs baseline: 1.1351x; 1.0018x over previous
#include <cuda_runtime.h>
#include <cuda_fp16.h>
#include <mma.h>
#include <math_constants.h>
#include <cstdint>
#include <cstddef>

using namespace nvcuda;

// Problem constants
#define KB 8
#define KS 4096
#define KH 16
#define KD 1024
#define KM 32768      // B*S
#define KW 16

// Device scratch (allocation-free rules)
__device__ __align__(256) __half g_qkvh [(size_t)KM * 3072];  // fp16 QKV (+bias)
__device__ __align__(256) __half g_xh   [(size_t)KM * KD];    // x in fp16
__device__ __align__(256) __half g_attnh[(size_t)KM * KD];    // attention out fp16
__device__ __align__(256) __half g_wqkvh[1024 * 3072];        // Wqkv fp16 [K][N]
__device__ __align__(256) __half g_woh  [1024 * 1024];        // Wo   fp16 [K][N]

// ---------------------------------------------------------------------------
// PTX helpers
// ---------------------------------------------------------------------------
__device__ __forceinline__ uint32_t smem_u32(const void* p) {
    return (uint32_t)__cvta_generic_to_shared((void*)p);
}
__device__ __forceinline__ void cp_async16(uint32_t dst, const void* src) {
    asm volatile("cp.async.cg.shared.global [%0], [%1], 16;\n" :: "r"(dst), "l"(src) : "memory");
}
__device__ __forceinline__ void cp_commit() { asm volatile("cp.async.commit_group;\n" ::: "memory"); }
__device__ __forceinline__ void cp_wait0()  { asm volatile("cp.async.wait_group 0;\n" ::: "memory"); }
__device__ __forceinline__ void cp_wait1()  { asm volatile("cp.async.wait_group 1;\n" ::: "memory"); }

__device__ __forceinline__ void ldsm_x4(uint32_t& r0, uint32_t& r1, uint32_t& r2, uint32_t& r3,
                                        uint32_t addr) {
    asm volatile("ldmatrix.sync.aligned.m8n8.x4.shared.b16 {%0,%1,%2,%3}, [%4];"
                 : "=r"(r0), "=r"(r1), "=r"(r2), "=r"(r3) : "r"(addr));
}
__device__ __forceinline__ void ldsm_x4_t(uint32_t& r0, uint32_t& r1, uint32_t& r2, uint32_t& r3,
                                          uint32_t addr) {
    asm volatile("ldmatrix.sync.aligned.m8n8.x4.trans.shared.b16 {%0,%1,%2,%3}, [%4];"
                 : "=r"(r0), "=r"(r1), "=r"(r2), "=r"(r3) : "r"(addr));
}
__device__ __forceinline__ void mma16816(float* d, const uint32_t* a, uint32_t b0, uint32_t b1) {
    asm volatile("mma.sync.aligned.m16n8k16.row.col.f32.f16.f16.f32 "
                 "{%0,%1,%2,%3}, {%4,%5,%6,%7}, {%8,%9}, {%0,%1,%2,%3};"
                 : "+f"(d[0]), "+f"(d[1]), "+f"(d[2]), "+f"(d[3])
                 : "r"(a[0]), "r"(a[1]), "r"(a[2]), "r"(a[3]), "r"(b0), "r"(b1));
}
__device__ __forceinline__ uint32_t pack_h2(float a, float b) {
    __half2 h = __floats2half2_rn(a, b);
    return *reinterpret_cast<uint32_t*>(&h);
}

// ---------------------------------------------------------------------------
// fp32 -> fp16 convert, 3 arrays in ONE launch (grid-stride per segment)
// ---------------------------------------------------------------------------
__global__ void f2h3(const float* __restrict__ a, __half* __restrict__ oa, int na,
                     const float* __restrict__ b, __half* __restrict__ ob, int nb,
                     const float* __restrict__ c, __half* __restrict__ oc, int nc)
{
    const int stride = gridDim.x * blockDim.x * 4;
    const int base = (blockIdx.x * blockDim.x + threadIdx.x) * 4;
#pragma unroll 1
    for (int i = base; i < na; i += stride) {
        float4 v = *(const float4*)(a + i);
        __half2 h0 = __floats2half2_rn(v.x, v.y);
        __half2 h1 = __floats2half2_rn(v.z, v.w);
        uint2 u = { *reinterpret_cast<uint32_t*>(&h0), *reinterpret_cast<uint32_t*>(&h1) };
        *(uint2*)(oa + i) = u;
    }
#pragma unroll 1
    for (int i = base; i < nb; i += stride) {
        float4 v = *(const float4*)(b + i);
        __half2 h0 = __floats2half2_rn(v.x, v.y);
        __half2 h1 = __floats2half2_rn(v.z, v.w);
        uint2 u = { *reinterpret_cast<uint32_t*>(&h0), *reinterpret_cast<uint32_t*>(&h1) };
        *(uint2*)(ob + i) = u;
    }
#pragma unroll 1
    for (int i = base; i < nc; i += stride) {
        float4 v = *(const float4*)(c + i);
        __half2 h0 = __floats2half2_rn(v.x, v.y);
        __half2 h1 = __floats2half2_rn(v.z, v.w);
        uint2 u = { *reinterpret_cast<uint32_t*>(&h0), *reinterpret_cast<uint32_t*>(&h1) };
        *(uint2*)(oc + i) = u;
    }
}

// ---------------------------------------------------------------------------
// Common stage geometry (BK=64)
// ---------------------------------------------------------------------------
#define G_LDA 72
#define G_LDB 136
#define G_ASZ (128 * G_LDA * 2)
#define G_STG (G_ASZ + 64 * G_LDB * 2)
#define G_SMEM (3 * G_STG)

// ---------------------------------------------------------------------------
// GEMM variant A (round 11): 256 thr, 8 warps 2x4, warp tile 64x32. (GEMM2)
// ---------------------------------------------------------------------------
template<bool HALF_OUT>
__global__ __launch_bounds__(256, 2)
void gemm_k64(const __half* __restrict__ A, const __half* __restrict__ Bw,
              const float* __restrict__ bias, void* __restrict__ Cv,
              int N, int K)
{
    extern __shared__ __align__(16) char sm[];
    const uint32_t sbase = smem_u32(sm);
    const int tid    = threadIdx.x;
    const int warpId = tid >> 5;
    const int lane   = tid & 31;
    const int warpM  = warpId & 1;
    const int warpN  = warpId >> 1;
    const int m0 = blockIdx.y * 128;
    const int n0 = blockIdx.x * 128;
    const int nT = K >> 6;

    auto fill = [&](int t, int slot) {
        const int k0 = t << 6;
        const uint32_t sb = sbase + (uint32_t)slot * G_STG;
#pragma unroll
        for (int u = 0; u < 4; u++) {
            int i = tid + u * 256;
            int r = i >> 3, c = (i & 7) * 8;
            cp_async16(sb + r * (G_LDA * 2) + c * 2, A + (size_t)(m0 + r) * K + k0 + c);
        }
#pragma unroll
        for (int u = 0; u < 4; u++) {
            int i = tid + u * 256;
            int r = i >> 4, c = (i & 15) * 8;
            cp_async16(sb + G_ASZ + r * (G_LDB * 2) + c * 2,
                       Bw + (size_t)(k0 + r) * N + n0 + c);
        }
    };

    fill(0, 0); cp_commit();
    fill(1, 1); cp_commit();

    wmma::fragment<wmma::accumulator, 16, 16, 16, float> cf[4][2];
#pragma unroll
    for (int i = 0; i < 4; i++)
#pragma unroll
        for (int j = 0; j < 2; j++)
            wmma::fill_fragment(cf[i][j], 0.0f);

    for (int t = 0; t < nT; t++) {
        const int slot = t % 3;
        if (t + 1 < nT) cp_wait1(); else cp_wait0();
        __syncthreads();
        if (t + 2 < nT) { fill(t + 2, (t + 2) % 3); cp_commit(); }

        const __half* As_ = (const __half*)(sm + (size_t)slot * G_STG);
        const __half* Bs_ = (const __half*)(sm + (size_t)slot * G_STG + G_ASZ);
#pragma unroll
        for (int kk = 0; kk < 4; kk++) {
            wmma::fragment<wmma::matrix_b, 16, 16, 16, __half, wmma::row_major> bf[2];
#pragma unroll
            for (int j = 0; j < 2; j++)
                wmma::load_matrix_sync(bf[j], &Bs_[(kk * 16) * G_LDB + warpN * 32 + j * 16], G_LDB);
#pragma unroll
            for (int i = 0; i < 4; i++) {
                wmma::fragment<wmma::matrix_a, 16, 16, 16, __half, wmma::row_major> af;
                wmma::load_matrix_sync(af, &As_[(warpM * 64 + i * 16) * G_LDA + kk * 16], G_LDA);
#pragma unroll
                for (int j = 0; j < 2; j++)
                    wmma::mma_sync(cf[i][j], af, bf[j], cf[i][j]);
            }
        }
    }

    __syncthreads();

    float* stg = (float*)sm + warpId * 320;
    const int r  = lane >> 1;
    const int c8 = (lane & 1) * 8;
#pragma unroll
    for (int j = 0; j < 2; j++) {
        const float* bp = bias + n0 + warpN * 32 + j * 16 + c8;
        const float4 b0 = *(const float4*)bp;
        const float4 b1 = *(const float4*)(bp + 4);
#pragma unroll
        for (int i = 0; i < 4; i++) {
            wmma::store_matrix_sync(stg, cf[i][j], 20, wmma::mem_row_major);
            __syncwarp();
            const float* s = stg + r * 20 + c8;
            float v0 = s[0] + b0.x, v1 = s[1] + b0.y, v2 = s[2] + b0.z, v3 = s[3] + b0.w;
            float v4 = s[4] + b1.x, v5 = s[5] + b1.y, v6 = s[6] + b1.z, v7 = s[7] + b1.w;
            const size_t row = (size_t)(m0 + warpM * 64 + i * 16 + r);
            const int    col = n0 + warpN * 32 + j * 16 + c8;
            if (HALF_OUT) {
                __half2 h0 = __floats2half2_rn(v0, v1);
                __half2 h1 = __floats2half2_rn(v2, v3);
                __half2 h2 = __floats2half2_rn(v4, v5);
                __half2 h3 = __floats2half2_rn(v6, v7);
                uint4 u;
                u.x = *reinterpret_cast<uint32_t*>(&h0);
                u.y = *reinterpret_cast<uint32_t*>(&h1);
                u.z = *reinterpret_cast<uint32_t*>(&h2);
                u.w = *reinterpret_cast<uint32_t*>(&h3);
                *(uint4*)((__half*)Cv + row * N + col) = u;
            } else {
                *(float4*)((float*)Cv + row * N + col)     = make_float4(v0, v1, v2, v3);
                *(float4*)((float*)Cv + row * N + col + 4) = make_float4(v4, v5, v6, v7);
            }
            __syncwarp();
        }
    }
}

// ---------------------------------------------------------------------------
// GEMM variant B (round 13 best): 128 thr, 4 warps 2x2, warp tile 64x64. (GEMM1)
// ---------------------------------------------------------------------------
template<bool HALF_OUT>
__global__ __launch_bounds__(128, 2)
void gemm_w64(const __half* __restrict__ A, const __half* __restrict__ Bw,
              const float* __restrict__ bias, void* __restrict__ Cv,
              int N, int K)
{
    extern __shared__ __align__(16) char sm[];
    const uint32_t sbase = smem_u32(sm);
    const int tid    = threadIdx.x;
    const int warpId = tid >> 5;
    const int lane   = tid & 31;
    const int wm = warpId & 1;
    const int wn = warpId >> 1;
    const int m0 = blockIdx.y * 128;
    const int n0 = blockIdx.x * 128;
    const int nT = K >> 6;

    auto fill = [&](int t, int slot) {
        const int k0 = t << 6;
        const uint32_t sb = sbase + (uint32_t)slot * G_STG;
#pragma unroll
        for (int u = 0; u < 8; u++) {
            int i = tid + u * 128;
            int r = i >> 3, c = (i & 7) * 8;
            cp_async16(sb + r * (G_LDA * 2) + c * 2, A + (size_t)(m0 + r) * K + k0 + c);
        }
#pragma unroll
        for (int u = 0; u < 8; u++) {
            int i = tid + u * 128;
            int r = i >> 4, c = (i & 15) * 8;
            cp_async16(sb + G_ASZ + r * (G_LDB * 2) + c * 2,
                       Bw + (size_t)(k0 + r) * N + n0 + c);
        }
    };

    fill(0, 0); cp_commit();
    fill(1, 1); cp_commit();

    wmma::fragment<wmma::accumulator, 16, 16, 16, float> cf[4][4];
#pragma unroll
    for (int i = 0; i < 4; i++)
#pragma unroll
        for (int j = 0; j < 4; j++)
            wmma::fill_fragment(cf[i][j], 0.0f);

    for (int t = 0; t < nT; t++) {
        const int slot = t % 3;
        if (t + 1 < nT) cp_wait1(); else cp_wait0();
        __syncthreads();
        if (t + 2 < nT) { fill(t + 2, (t + 2) % 3); cp_commit(); }

        const __half* As_ = (const __half*)(sm + (size_t)slot * G_STG);
        const __half* Bs_ = (const __half*)(sm + (size_t)slot * G_STG + G_ASZ);
#pragma unroll
        for (int kk = 0; kk < 4; kk++) {
            wmma::fragment<wmma::matrix_b, 16, 16, 16, __half, wmma::row_major> bf[4];
#pragma unroll
            for (int j = 0; j < 4; j++)
                wmma::load_matrix_sync(bf[j], &Bs_[(kk * 16) * G_LDB + wn * 64 + j * 16], G_LDB);
#pragma unroll
            for (int i = 0; i < 4; i++) {
                wmma::fragment<wmma::matrix_a, 16, 16, 16, __half, wmma::row_major> af;
                wmma::load_matrix_sync(af, &As_[(wm * 64 + i * 16) * G_LDA + kk * 16], G_LDA);
#pragma unroll
                for (int j = 0; j < 4; j++)
                    wmma::mma_sync(cf[i][j], af, bf[j], cf[i][j]);
            }
        }
    }

    __syncthreads();

    float* stg = (float*)sm + warpId * 320;
    const int r  = lane >> 1;
    const int c8 = (lane & 1) * 8;
#pragma unroll
    for (int j = 0; j < 4; j++) {
        const float* bp = bias + n0 + wn * 64 + j * 16 + c8;
        const float4 b0 = *(const float4*)bp;
        const float4 b1 = *(const float4*)(bp + 4);
#pragma unroll
        for (int i = 0; i < 4; i++) {
            wmma::store_matrix_sync(stg, cf[i][j], 20, wmma::mem_row_major);
            __syncwarp();
            const float* s = stg + r * 20 + c8;
            float v0 = s[0] + b0.x, v1 = s[1] + b0.y, v2 = s[2] + b0.z, v3 = s[3] + b0.w;
            float v4 = s[4] + b1.x, v5 = s[5] + b1.y, v6 = s[6] + b1.z, v7 = s[7] + b1.w;
            const size_t row = (size_t)(m0 + wm * 64 + i * 16 + r);
            const int    col = n0 + wn * 64 + j * 16 + c8;
            if (HALF_OUT) {
                __half2 h0 = __floats2half2_rn(v0, v1);
                __half2 h1 = __floats2half2_rn(v2, v3);
                __half2 h2 = __floats2half2_rn(v4, v5);
                __half2 h3 = __floats2half2_rn(v6, v7);
                uint4 u;
                u.x = *reinterpret_cast<uint32_t*>(&h0);
                u.y = *reinterpret_cast<uint32_t*>(&h1);
                u.z = *reinterpret_cast<uint32_t*>(&h2);
                u.w = *reinterpret_cast<uint32_t*>(&h3);
                *(uint4*)((__half*)Cv + row * N + col) = u;
            } else {
                *(float4*)((float*)Cv + row * N + col)     = make_float4(v0, v1, v2, v3);
                *(float4*)((float*)Cv + row * N + col + 4) = make_float4(v4, v5, v6, v7);
            }
            __syncwarp();
        }
    }
}

// ---------------------------------------------------------------------------
// Banded FA sliding-window attention v3.
// Block = 128 queries x (b,h), 256 threads (8 warps). K/V rows s0-16..s0+143
// (160 rows). Warp w (rows wr=16w..wr+15) computes its 48-key band only.
// Two cp.async groups: Q+K first (S-phase starts while V is in flight).
// Register softmax; dynamic smem 64.5KB.
// ---------------------------------------------------------------------------
#define AQH 0                       // Q: 128 x 72 halves = 18432 B
#define AKH 18432                   // K: 160 x 72 halves = 23040 B
#define AVH 41472                   // V: 160 x 72 halves = 23040 B
#define ATT_SMEM 64512

__global__ __launch_bounds__(256)
void attn_fa()
{
    extern __shared__ __align__(16) char asm_[];
    const uint32_t qs = smem_u32(asm_ + AQH);
    const uint32_t ks = smem_u32(asm_ + AKH);
    const uint32_t vs = smem_u32(asm_ + AVH);

    const int b  = blockIdx.z;
    const int h  = blockIdx.y;
    const int s0 = blockIdx.x * 128;
    const int tid  = threadIdx.x;
    const int w    = tid >> 5;
    const int lane = tid & 31;
    const int wr   = w * 16;

    // ---- group 1: Q (128x64) + K (160x64) ----
    const __half* qbase = g_qkvh + (size_t)(b * KS) * 3072 + h * 192;
#pragma unroll
    for (int u = 0; u < 4; u++) {
        int i = tid + u * 256;
        int r = i >> 3, c = (i & 7) * 8;
        cp_async16(qs + (uint32_t)(r * 72 + c) * 2,
                   qbase + (size_t)(s0 + r) * 3072 + c);
    }
#pragma unroll
    for (int u = 0; u < 5; u++) {
        int i = tid + u * 256;
        int r = i >> 3, c = (i & 7) * 8;
        int key = s0 - KW + r;
        key = key < 0 ? 0 : (key >= KS ? KS - 1 : key);   // clamp; masked later
        cp_async16(ks + (uint32_t)(r * 72 + c) * 2,
                   qbase + (size_t)key * 3072 + 64 + c);
    }
    cp_commit();
    // ---- group 2: V (160x64) ----
#pragma unroll
    for (int u = 0; u < 5; u++) {
        int i = tid + u * 256;
        int r = i >> 3, c = (i & 7) * 8;
        int key = s0 - KW + r;
        key = key < 0 ? 0 : (key >= KS ? KS - 1 : key);
        cp_async16(vs + (uint32_t)(r * 72 + c) * 2,
                   qbase + (size_t)key * 3072 + 128 + c);
    }
    cp_commit();

    cp_wait1();           // Q+K landed; V still in flight
    __syncthreads();

    const int li = lane & 7;
    const int lg = lane >> 3;
    const int lr = lane >> 2;
    const int lc = lane & 3;

    // ---- Q A-fragments ----
    uint32_t af[4][4];
#pragma unroll
    for (int kt = 0; kt < 4; kt++) {
        int row = wr + (lg & 1) * 8 + li;
        int col = kt * 16 + (lg >> 1) * 8;
        ldsm_x4(af[kt][0], af[kt][1], af[kt][2], af[kt][3],
                qs + (uint32_t)(row * 72 + col) * 2);
    }

    // ---- S = Q @ K^T over the 48-key band [wr, wr+47] ----
    float sacc[6][4];
#pragma unroll
    for (int na = 0; na < 6; na++)
#pragma unroll
        for (int e = 0; e < 4; e++) sacc[na][e] = 0.0f;

#pragma unroll
    for (int nn = 0; nn < 3; nn++) {
        const int n0 = wr + nn * 16;
#pragma unroll
        for (int kt = 0; kt < 4; kt++) {
            uint32_t b0, b1, b2, b3;
            int row = n0 + (lg >> 1) * 8 + li;
            int col = kt * 16 + (lg & 1) * 8;
            ldsm_x4(b0, b1, b2, b3, ks + (uint32_t)(row * 72 + col) * 2);
            mma16816(sacc[2 * nn],     af[kt], b0, b1);
            mma16816(sacc[2 * nn + 1], af[kt], b2, b3);
        }
    }

    // ---- masked softmax in fragments (rows rA, rA+8) ----
    const int rA = wr + lr;
    float mx0 = -1e30f, mx1 = -1e30f;
#pragma unroll
    for (int na = 0; na < 6; na++) {
        const int j0 = wr + na * 8 + lc * 2;
        const int j1 = j0 + 1;
        const int k0g = s0 - KW + j0, k1g = k0g + 1;
        bool v00 = (j0 >= rA) && (j0 <= rA + 32) && (k0g >= 0) && (k0g < KS);
        bool v01 = (j1 >= rA) && (j1 <= rA + 32) && (k1g >= 0) && (k1g < KS);
        bool v10 = (j0 >= rA + 8) && (j0 <= rA + 40) && (k0g >= 0) && (k0g < KS);
        bool v11 = (j1 >= rA + 8) && (j1 <= rA + 40) && (k1g >= 0) && (k1g < KS);
        sacc[na][0] = v00 ? sacc[na][0] : -1e30f;
        sacc[na][1] = v01 ? sacc[na][1] : -1e30f;
        sacc[na][2] = v10 ? sacc[na][2] : -1e30f;
        sacc[na][3] = v11 ? sacc[na][3] : -1e30f;
        mx0 = fmaxf(mx0, fmaxf(sacc[na][0], sacc[na][1]));
        mx1 = fmaxf(mx1, fmaxf(sacc[na][2], sacc[na][3]));
    }
    mx0 = fmaxf(mx0, __shfl_xor_sync(0xffffffffu, mx0, 1));
    mx0 = fmaxf(mx0, __shfl_xor_sync(0xffffffffu, mx0, 2));
    mx1 = fmaxf(mx1, __shfl_xor_sync(0xffffffffu, mx1, 1));
    mx1 = fmaxf(mx1, __shfl_xor_sync(0xffffffffu, mx1, 2));

    float sum0 = 0.0f, sum1 = 0.0f;
#pragma unroll
    for (int na = 0; na < 6; na++) {
        float e0 = __expf(0.125f * (sacc[na][0] - mx0));
        float e1 = __expf(0.125f * (sacc[na][1] - mx0));
        float e2 = __expf(0.125f * (sacc[na][2] - mx1));
        float e3 = __expf(0.125f * (sacc[na][3] - mx1));
        sacc[na][0] = e0; sacc[na][1] = e1; sacc[na][2] = e2; sacc[na][3] = e3;
        sum0 += e0 + e1; sum1 += e2 + e3;
    }
    sum0 += __shfl_xor_sync(0xffffffffu, sum0, 1);
    sum0 += __shfl_xor_sync(0xffffffffu, sum0, 2);
    sum1 += __shfl_xor_sync(0xffffffffu, sum1, 1);
    sum1 += __shfl_xor_sync(0xffffffffu, sum1, 2);
    const float inv0 = 1.0f / sum0;
    const float inv1 = 1.0f / sum1;
#pragma unroll
    for (int na = 0; na < 6; na++) {
        sacc[na][0] *= inv0; sacc[na][1] *= inv0;
        sacc[na][2] *= inv1; sacc[na][3] *= inv1;
    }

    cp_wait0();           // V landed
    __syncthreads();

    // ---- O = P @ V over the band: V rows wr+kt*16, kt=0..2 ----
    float oacc[8][4];
#pragma unroll
    for (int na = 0; na < 8; na++)
#pragma unroll
        for (int e = 0; e < 4; e++) oacc[na][e] = 0.0f;

#pragma unroll
    for (int kt = 0; kt < 3; kt++) {
        uint32_t a[4];
        a[0] = pack_h2(sacc[2 * kt][0],     sacc[2 * kt][1]);
        a[1] = pack_h2(sacc[2 * kt][2],     sacc[2 * kt][3]);
        a[2] = pack_h2(sacc[2 * kt + 1][0], sacc[2 * kt + 1][1]);
        a[3] = pack_h2(sacc[2 * kt + 1][2], sacc[2 * kt + 1][3]);
        const int k0 = wr + kt * 16;
#pragma unroll
        for (int np = 0; np < 4; np++) {
            const int n0 = np * 16;
            uint32_t b0, b1, b2, b3;
            int row = k0 + (lg & 1) * 8 + li;
            int col = n0 + (lg >> 1) * 8;
            ldsm_x4_t(b0, b1, b2, b3, vs + (uint32_t)(row * 72 + col) * 2);
            mma16816(oacc[2 * np],     a, b0, b1);
            mma16816(oacc[2 * np + 1], a, b2, b3);
        }
    }

    // ---- store fp16 output ----
    __half* op = g_attnh + (size_t)(b * KS + s0) * KD + h * 64;
#pragma unroll
    for (int na = 0; na < 8; na++) {
        const int col = na * 8 + lc * 2;
        __half2 h0 = __floats2half2_rn(oacc[na][0], oacc[na][1]);
        __half2 h1 = __floats2half2_rn(oacc[na][2], oacc[na][3]);
        *(__half2*)(op + (size_t)rA * KD + col)       = h0;
        *(__half2*)(op + (size_t)(rA + 8) * KD + col) = h1;
    }
}

// ---------------------------------------------------------------------------
extern "C" void kernel_launch(void* const* d_in, const int* in_sizes, int n_in,
                              void* d_out, int out_size)
{
    const float* x    = (const float*)d_in[0];
    const float* Wqkv = (const float*)d_in[1];
    const float* bqkv = (const float*)d_in[2];
    const float* Wo   = (const float*)d_in[3];
    const float* bo   = (const float*)d_in[4];
    float* out = (float*)d_out;

    void *p_qkvh, *p_xh, *p_attnh, *p_wqkvh, *p_woh;
    cudaGetSymbolAddress(&p_qkvh,  g_qkvh);
    cudaGetSymbolAddress(&p_xh,    g_xh);
    cudaGetSymbolAddress(&p_attnh, g_attnh);
    cudaGetSymbolAddress(&p_wqkvh, g_wqkvh);
    cudaGetSymbolAddress(&p_woh,   g_woh);

    cudaFuncSetAttribute(gemm_w64<true>,  cudaFuncAttributeMaxDynamicSharedMemorySize, G_SMEM);
    cudaFuncSetAttribute(gemm_k64<false>, cudaFuncAttributeMaxDynamicSharedMemorySize, G_SMEM);
    cudaFuncSetAttribute(attn_fa, cudaFuncAttributeMaxDynamicSharedMemorySize, ATT_SMEM);

    // 0) fp32 -> fp16 converts (x, Wqkv, Wo) in ONE launch
    f2h3<<<4096, 256>>>(x,    (__half*)p_xh,    KM * KD,
                        Wqkv, (__half*)p_wqkvh, 1024 * 3072,
                        Wo,   (__half*)p_woh,   1024 * 1024);

    // 1) QKV projection (fp16 out): round-13 best geometry
    gemm_w64<true><<<dim3(3072 / 128, KM / 128), 128, G_SMEM>>>(
        (const __half*)p_xh, (const __half*)p_wqkvh, bqkv, p_qkvh, 3072, 1024);

    // 2) Banded FA attention, 128-query blocks -> g_attnh
    attn_fa<<<dim3(KS / 128, KH, KB), 256, ATT_SMEM>>>();

    // 3) Output projection (fp32 out): round-11 geometry
    gemm_k64<false><<<dim3(1024 / 128, KM / 128), 256, G_SMEM>>>(
        (const __half*)p_attnh, (const __half*)p_woh, bo, out, 1024, 1024);
}